// round 9
// baseline (speedup 1.0000x reference)
#include <cuda_runtime.h>
#include <cuda_bf16.h>
#include <math.h>
#include <stdint.h>

#define NN    8192
#define DIM   64
#define TOPK  64
#define CCAP  512           // global candidate capacity per row
#define SCAP  160           // shared survivor capacity per row (proven <=128)
#define SCREEN_I 7000       // int screen: 7000/16129=0.434 < 0.5-0.064 bound
#define TS    128
#define PAD8  40            // b16 pitch of int8 tile rows (80B; ldsm conflict-free)
#define NTILE (NN / TS)     // 64
#define NJOBS (NTILE * (NTILE + 1) / 2)   // 2080

// ---- static device scratch ----
__device__ float   g_hn[NN * DIM];                  // fp32 hn (exact recheck)
__device__ __align__(16) int8_t g_hni8[NN * DIM];   // s8 hn (TC screen)
__device__ int     g_candJ[NN * CCAP];
__device__ int     g_ccnt[NN];

// ---------------------------------------------------------------------------
// helpers (baseline compute_100: ldmatrix sm_75+, s8 mma sm_80+)
// ---------------------------------------------------------------------------
__device__ __forceinline__ uint32_t smem_u32(const void* p) {
    uint32_t a;
    asm("{ .reg .u64 t; cvta.to.shared.u64 t, %1; cvt.u32.u64 %0, t; }"
        : "=r"(a) : "l"(p));
    return a;
}
__device__ __forceinline__ void ldsm4(uint32_t* r, uint32_t addr) {
    asm volatile("ldmatrix.sync.aligned.m8n8.x4.shared.b16 {%0,%1,%2,%3}, [%4];"
                 : "=r"(r[0]), "=r"(r[1]), "=r"(r[2]), "=r"(r[3]) : "r"(addr));
}
__device__ __forceinline__ void mma_s8(int* c, const uint32_t* a, const uint32_t* b) {
    asm volatile(
        "mma.sync.aligned.m16n8k32.row.col.s32.s8.s8.s32 "
        "{%0,%1,%2,%3}, {%4,%5,%6,%7}, {%8,%9}, {%0,%1,%2,%3};"
        : "+r"(c[0]), "+r"(c[1]), "+r"(c[2]), "+r"(c[3])
        : "r"(a[0]), "r"(a[1]), "r"(a[2]), "r"(a[3]), "r"(b[0]), "r"(b[1]));
}
// pack 4 floats (in [-1,1]) -> 4 s8 bytes, memory order v0..v3
__device__ __forceinline__ uint32_t pack_s8x4(float v0, float v1, float v2, float v3) {
    int q0 = __float2int_rn(v0 * 127.0f);
    int q1 = __float2int_rn(v1 * 127.0f);
    int q2 = __float2int_rn(v2 * 127.0f);
    int q3 = __float2int_rn(v3 * 127.0f);
    return (uint32_t)(q0 & 0xFF) | ((uint32_t)(q1 & 0xFF) << 8) |
           ((uint32_t)(q2 & 0xFF) << 16) | ((uint32_t)(q3 & 0xFF) << 24);
}

// ---------------------------------------------------------------------------
// Kernel 1: hn = normalize(tanh(3*(emb[idx]@W^T + b))), fp32 + s8 outputs.
// 512 blocks x 16 rows. Also zeroes H and g_ccnt. idx is int32.
// ---------------------------------------------------------------------------
__global__ void __launch_bounds__(256) hn_kernel(
    const int* __restrict__ idx,
    const float* __restrict__ emb,
    const float* __restrict__ W,
    const float* __restrict__ bias,
    float* __restrict__ H)
{
    __shared__ float WsT[64 * 72];
    __shared__ float xs[16][64];
    __shared__ int   s_src[16];
    __shared__ float s_bias[64];

    int t = threadIdx.x;

    ((float4*)H)[blockIdx.x * 256 + t] = make_float4(0.f, 0.f, 0.f, 0.f);
    if (blockIdx.x < 8)
        ((int4*)g_ccnt)[blockIdx.x * 256 + t] = make_int4(0, 0, 0, 0);

    if (t < 16) s_src[t] = idx[blockIdx.x * 16 + t] & (NN - 1);
    if (t < 64) s_bias[t] = bias[t];

    #pragma unroll
    for (int q = 0; q < 16; q++) {
        int e = q * 256 + t;
        WsT[(e & 63) * 72 + (e >> 6)] = W[e];
    }
    __syncthreads();

    #pragma unroll
    for (int q = 0; q < 4; q++) {
        int e = q * 256 + t;
        int r = e >> 6, k = e & 63;
        xs[r][k] = emb[s_src[r] * DIM + k];
    }
    __syncthreads();

    int r  = t >> 4;
    int d0 = (t & 15) * 4;

    float a0 = s_bias[d0], a1 = s_bias[d0 + 1], a2 = s_bias[d0 + 2], a3 = s_bias[d0 + 3];
    #pragma unroll
    for (int k = 0; k < 64; k++) {
        float  xv = xs[r][k];
        float4 w4 = *(const float4*)&WsT[k * 72 + d0];
        a0 += xv * w4.x; a1 += xv * w4.y; a2 += xv * w4.z; a3 += xv * w4.w;
    }

    float h0 = tanhf(3.0f * a0), h1 = tanhf(3.0f * a1);
    float h2 = tanhf(3.0f * a2), h3 = tanhf(3.0f * a3);

    float sq = h0 * h0 + h1 * h1 + h2 * h2 + h3 * h3;
    #pragma unroll
    for (int o = 8; o; o >>= 1)
        sq += __shfl_xor_sync(0xffffffffu, sq, o);

    float nrm = fmaxf(sqrtf(sq), 1e-8f);
    float v0 = h0 / nrm, v1 = h1 / nrm, v2 = h2 / nrm, v3 = h3 / nrm;

    int row = blockIdx.x * 16 + r;
    *(float4*)&g_hn[row * DIM + d0] = make_float4(v0, v1, v2, v3);
    *(uint32_t*)&g_hni8[row * DIM + d0] = pack_s8x4(v0, v1, v2, v3);
}

// ---------------------------------------------------------------------------
// Kernel 2: s8 MMA screen, symmetric triangular 128x128 tiles (2080 blocks).
// 8 warps x (64x32) via m16n8k32.s8. simq >= 7000 -> push candidates to both
// rows' lists (diagonal: j>=i).
// ---------------------------------------------------------------------------
__device__ __forceinline__ void screen_push(int gi, int gj, int v, bool diag)
{
    if (v >= SCREEN_I) {
        if (!diag || gj > gi) {
            int p = atomicAdd(&g_ccnt[gi], 1);
            if (p < CCAP) g_candJ[gi * CCAP + p] = gj;
            p = atomicAdd(&g_ccnt[gj], 1);
            if (p < CCAP) g_candJ[gj * CCAP + p] = gi;
        } else if (gj == gi) {
            int p = atomicAdd(&g_ccnt[gi], 1);
            if (p < CCAP) g_candJ[gi * CCAP + p] = gi;
        }
    }
}

__global__ void __launch_bounds__(256) sim_mma_kernel()
{
    __shared__ __align__(16) uint16_t sA[TS * PAD8];   // s8 tile, b16-view (10KB)
    __shared__ __align__(16) uint16_t sB[TS * PAD8];

    int b = blockIdx.x, ti = 0;
    while (b >= NTILE - ti) { b -= NTILE - ti; ti++; }
    int tj = ti + b;
    int ib = ti * TS, jb = tj * TS;

    int t = threadIdx.x, wid = t >> 5, l = t & 31;

    // load tiles: 128 rows x 64B each = 2 uint4 per thread per tile
    #pragma unroll
    for (int q = 0; q < 2; q++) {
        int id  = q * 256 + t;
        int row = id >> 2, c = (id & 3) * 16;
        *(uint4*)((char*)sA + row * 80 + c) = *(const uint4*)(g_hni8 + (ib + row) * DIM + c);
        *(uint4*)((char*)sB + row * 80 + c) = *(const uint4*)(g_hni8 + (jb + row) * DIM + c);
    }
    __syncthreads();

    int wr = wid >> 2, wc = wid & 3;
    int R0 = wr * 64, C0 = wc * 32;

    int acc[4][4][4];
    #pragma unroll
    for (int mt = 0; mt < 4; mt++)
        #pragma unroll
        for (int nt = 0; nt < 4; nt++)
            #pragma unroll
            for (int e = 0; e < 4; e++) acc[mt][nt][e] = 0;

    uint32_t aBase = smem_u32(sA);
    uint32_t bBase = smem_u32(sB);

    int lr    = l & 7;
    int khalf = (l >> 3) & 1;
    int kq    = l >> 4;

    #pragma unroll
    for (int ks = 0; ks < 2; ks++) {       // K=64 s8 = 32 b16 units; 16 per step
        int k0 = ks * 16;                  // b16 units

        uint32_t af[4][4];
        #pragma unroll
        for (int mt = 0; mt < 4; mt++) {
            uint32_t addr = aBase +
                (uint32_t)(((R0 + mt * 16 + lr + khalf * 8) * PAD8 + k0 + kq * 8) * 2);
            ldsm4(af[mt], addr);
        }

        uint32_t bf[4][2];
        #pragma unroll
        for (int np = 0; np < 2; np++) {
            uint32_t r4[4];
            uint32_t addr = bBase +
                (uint32_t)(((C0 + np * 16 + kq * 8 + lr) * PAD8 + k0 + khalf * 8) * 2);
            ldsm4(r4, addr);
            bf[np * 2 + 0][0] = r4[0]; bf[np * 2 + 0][1] = r4[1];
            bf[np * 2 + 1][0] = r4[2]; bf[np * 2 + 1][1] = r4[3];
        }

        #pragma unroll
        for (int mt = 0; mt < 4; mt++)
            #pragma unroll
            for (int nt = 0; nt < 4; nt++)
                mma_s8(acc[mt][nt], af[mt], bf[nt]);
    }

    bool diag = (ti == tj);
    int gr = l >> 2, tg = l & 3;
    #pragma unroll
    for (int mt = 0; mt < 4; mt++) {
        int gi0 = ib + R0 + mt * 16 + gr;
        #pragma unroll
        for (int nt = 0; nt < 4; nt++) {
            int gj0 = jb + C0 + nt * 8 + tg * 2;
            int* c = acc[mt][nt];
            screen_push(gi0,     gj0,     c[0], diag);
            screen_push(gi0,     gj0 + 1, c[1], diag);
            screen_push(gi0 + 8, gj0,     c[2], diag);
            screen_push(gi0 + 8, gj0 + 1, c[3], diag);
        }
    }
}

// ---------------------------------------------------------------------------
// Kernel 3: exact fp32 recheck (candidates from global) + per-row top-64
// with JAX stable tie-break. One warp per row.
// ---------------------------------------------------------------------------
__global__ void __launch_bounds__(256) topk_kernel(float* __restrict__ H)
{
    __shared__ float sV[8][SCAP];
    __shared__ int   sJ[8][SCAP];

    int t = threadIdx.x, w = t >> 5, l = t & 31;
    int r = blockIdx.x * 8 + w;
    const float* __restrict__ hn = g_hn;

    int m = g_ccnt[r];
    if (m > CCAP) m = CCAP;

    float a1 = hn[r * DIM + l];
    float a2 = hn[r * DIM + 32 + l];

    int cnt = 0;
    for (int p = 0; p < m; p++) {
        int j = g_candJ[r * CCAP + p];
        float s = a1 * hn[j * DIM + l] + a2 * hn[j * DIM + 32 + l];
        #pragma unroll
        for (int o = 16; o; o >>= 1)
            s += __shfl_xor_sync(0xffffffffu, s, o);
        if (s >= 0.5f && cnt < SCAP) {
            if (l == 0) { sV[w][cnt] = s; sJ[w][cnt] = j; }
            cnt++;
        }
    }
    __syncwarp();

    float* kv = sV[w];
    int*   kj = sJ[w];
    int nsel = cnt < TOPK ? cnt : TOPK;

    // selection: (value desc, index asc) — matches JAX top_k
    for (int s = 0; s < nsel; s++) {
        float bv = -1.0f; int bj = NN; int bp = -1;
        for (int p = l; p < cnt; p += 32) {
            float v = kv[p]; int j = kj[p];
            if (v > bv || (v == bv && j < bj)) { bv = v; bj = j; bp = p; }
        }
        #pragma unroll
        for (int o = 16; o; o >>= 1) {
            float ov = __shfl_xor_sync(0xffffffffu, bv, o);
            int   oj = __shfl_xor_sync(0xffffffffu, bj, o);
            int   op = __shfl_xor_sync(0xffffffffu, bp, o);
            if (ov > bv || (ov == bv && oj < bj)) { bv = ov; bj = oj; bp = op; }
        }
        if (l == 0) {
            H[s * NN + bj] = 1.0f;
            kv[bp] = -1.0f;
        }
        __syncwarp();
    }

    // fill remaining slots with zeros: ascending index, skipping survivors
    if (l == 0) {
        int s = nsel;
        int j = 0;
        while (s < TOPK) {
            bool kept = false;
            for (int p = 0; p < cnt; p++)
                if (kj[p] == j) { kept = true; break; }
            if (!kept) { H[s * NN + j] = 1.0f; s++; }
            j++;
        }
    }
}

// ---------------------------------------------------------------------------
// launch
// ---------------------------------------------------------------------------
extern "C" void kernel_launch(void* const* d_in, const int* in_sizes, int n_in,
                              void* d_out, int out_size)
{
    const int* idx    = (const int*)d_in[0];
    const float* emb  = (const float*)d_in[1];
    const float* W    = (const float*)d_in[2];
    const float* bias = (const float*)d_in[3];
    float* H          = (float*)d_out;

    hn_kernel<<<NN / 16, 256>>>(idx, emb, W, bias, H);
    sim_mma_kernel<<<NJOBS, 256>>>();
    topk_kernel<<<NN / 8, 256>>>(H);
}

// round 11
// speedup vs baseline: 1.2045x; 1.2045x over previous
#include <cuda_runtime.h>
#include <cuda_bf16.h>
#include <math.h>
#include <stdint.h>

#define NN    8192
#define DIM   64
#define TOPK  64
#define CCAP  256           // global candidate capacity per row
#define SCAP  160           // shared survivor staging in topk (true count <=128)
#define SCREEN 0.49f        // bf16 screen threshold (err bound ~2^-8, margin 0.01)
#define TS    128
#define PAD   72            // b16 pitch of tile rows (144B; ldsm conflict-free)
#define NTILE (NN / TS)     // 64
#define NJOBS (NTILE * (NTILE + 1) / 2)   // 2080

// ---- static device scratch ----
__device__ float         g_hn[NN * DIM];      // fp32 hn (exact recheck)
__device__ __nv_bfloat16 g_hnbf[NN * DIM];    // bf16 hn (TC screen)
__device__ int           g_candJ[NN * CCAP];
__device__ int           g_ccnt[NN];

// ---------------------------------------------------------------------------
// helpers (baseline compute_100: ldmatrix sm_75+, bf16 mma sm_80+)
// ---------------------------------------------------------------------------
__device__ __forceinline__ uint32_t smem_u32(const void* p) {
    uint32_t a;
    asm("{ .reg .u64 t; cvta.to.shared.u64 t, %1; cvt.u32.u64 %0, t; }"
        : "=r"(a) : "l"(p));
    return a;
}
__device__ __forceinline__ void ldsm4(uint32_t* r, uint32_t addr) {
    asm volatile("ldmatrix.sync.aligned.m8n8.x4.shared.b16 {%0,%1,%2,%3}, [%4];"
                 : "=r"(r[0]), "=r"(r[1]), "=r"(r[2]), "=r"(r[3]) : "r"(addr));
}
__device__ __forceinline__ void mma16816(float* c, const uint32_t* a, const uint32_t* b) {
    asm volatile(
        "mma.sync.aligned.m16n8k16.row.col.f32.bf16.bf16.f32 "
        "{%0,%1,%2,%3}, {%4,%5,%6,%7}, {%8,%9}, {%0,%1,%2,%3};"
        : "+f"(c[0]), "+f"(c[1]), "+f"(c[2]), "+f"(c[3])
        : "r"(a[0]), "r"(a[1]), "r"(a[2]), "r"(a[3]), "r"(b[0]), "r"(b[1]));
}

// ---------------------------------------------------------------------------
// Kernel 1: hn = normalize(tanh(3*(emb[idx]@W^T + b))), fp32 + bf16 outputs.
// 512 blocks x 16 rows. Also zeroes H and g_ccnt. idx is int32.
// ---------------------------------------------------------------------------
__global__ void __launch_bounds__(256) hn_kernel(
    const int* __restrict__ idx,
    const float* __restrict__ emb,
    const float* __restrict__ W,
    const float* __restrict__ bias,
    float* __restrict__ H)
{
    __shared__ float WsT[64 * 72];
    __shared__ float xs[16][64];
    __shared__ int   s_src[16];
    __shared__ float s_bias[64];

    int t = threadIdx.x;

    ((float4*)H)[blockIdx.x * 256 + t] = make_float4(0.f, 0.f, 0.f, 0.f);
    if (blockIdx.x < 8)
        ((int4*)g_ccnt)[blockIdx.x * 256 + t] = make_int4(0, 0, 0, 0);

    if (t < 16) s_src[t] = idx[blockIdx.x * 16 + t] & (NN - 1);
    if (t < 64) s_bias[t] = bias[t];

    #pragma unroll
    for (int q = 0; q < 16; q++) {
        int e = q * 256 + t;
        WsT[(e & 63) * 72 + (e >> 6)] = W[e];
    }
    __syncthreads();

    #pragma unroll
    for (int q = 0; q < 4; q++) {
        int e = q * 256 + t;
        int r = e >> 6, k = e & 63;
        xs[r][k] = emb[s_src[r] * DIM + k];
    }
    __syncthreads();

    int r  = t >> 4;
    int d0 = (t & 15) * 4;

    float a0 = s_bias[d0], a1 = s_bias[d0 + 1], a2 = s_bias[d0 + 2], a3 = s_bias[d0 + 3];
    #pragma unroll
    for (int k = 0; k < 64; k++) {
        float  xv = xs[r][k];
        float4 w4 = *(const float4*)&WsT[k * 72 + d0];
        a0 += xv * w4.x; a1 += xv * w4.y; a2 += xv * w4.z; a3 += xv * w4.w;
    }

    float h0 = tanhf(3.0f * a0), h1 = tanhf(3.0f * a1);
    float h2 = tanhf(3.0f * a2), h3 = tanhf(3.0f * a3);

    float sq = h0 * h0 + h1 * h1 + h2 * h2 + h3 * h3;
    #pragma unroll
    for (int o = 8; o; o >>= 1)
        sq += __shfl_xor_sync(0xffffffffu, sq, o);

    float nrm = fmaxf(sqrtf(sq), 1e-8f);
    float v0 = h0 / nrm, v1 = h1 / nrm, v2 = h2 / nrm, v3 = h3 / nrm;

    int row = blockIdx.x * 16 + r;
    *(float4*)&g_hn[row * DIM + d0] = make_float4(v0, v1, v2, v3);

    __nv_bfloat162* bp = (__nv_bfloat162*)&g_hnbf[row * DIM + d0];
    bp[0] = __nv_bfloat162(__float2bfloat16(v0), __float2bfloat16(v1));
    bp[1] = __nv_bfloat162(__float2bfloat16(v2), __float2bfloat16(v3));
}

// ---------------------------------------------------------------------------
// Kernel 2: bf16 HMMA screen, symmetric triangular 128x128 tiles (2080 blocks).
// 8 warps x (64x32) via m16n8k16. Ballot early-out epilogue — one
// warp-uniform branch per 16-value group instead of 64 divergent if-blocks.
// ---------------------------------------------------------------------------
__device__ __forceinline__ void screen_push(int gi, int gj, float v, bool diag)
{
    if (v >= SCREEN) {
        if (!diag || gj > gi) {
            int p = atomicAdd(&g_ccnt[gi], 1);
            if (p < CCAP) g_candJ[gi * CCAP + p] = gj;
            p = atomicAdd(&g_ccnt[gj], 1);
            if (p < CCAP) g_candJ[gj * CCAP + p] = gi;
        } else if (gj == gi) {
            int p = atomicAdd(&g_ccnt[gi], 1);
            if (p < CCAP) g_candJ[gi * CCAP + p] = gi;
        }
    }
}

__global__ void __launch_bounds__(256) sim_mma_kernel()
{
    __shared__ __nv_bfloat16 sA[TS * PAD];
    __shared__ __nv_bfloat16 sB[TS * PAD];

    int b = blockIdx.x, ti = 0;
    while (b >= NTILE - ti) { b -= NTILE - ti; ti++; }
    int tj = ti + b;
    int ib = ti * TS, jb = tj * TS;

    int t = threadIdx.x, wid = t >> 5, l = t & 31;

    const __nv_bfloat16* hb = g_hnbf;
    #pragma unroll
    for (int q = 0; q < 4; q++) {
        int id  = q * 256 + t;
        int row = id >> 3, c8 = (id & 7) * 8;
        *(uint4*)(sA + row * PAD + c8) = *(const uint4*)(hb + (ib + row) * DIM + c8);
        *(uint4*)(sB + row * PAD + c8) = *(const uint4*)(hb + (jb + row) * DIM + c8);
    }
    __syncthreads();

    int wr = wid >> 2, wc = wid & 3;
    int R0 = wr * 64, C0 = wc * 32;

    float acc[4][4][4];
    #pragma unroll
    for (int mt = 0; mt < 4; mt++)
        #pragma unroll
        for (int nt = 0; nt < 4; nt++)
            #pragma unroll
            for (int e = 0; e < 4; e++) acc[mt][nt][e] = 0.0f;

    uint32_t aBase = smem_u32(sA);
    uint32_t bBase = smem_u32(sB);

    int lr    = l & 7;
    int khalf = (l >> 3) & 1;
    int kq    = l >> 4;

    #pragma unroll
    for (int ks = 0; ks < 4; ks++) {
        int k0 = ks * 16;

        uint32_t af[4][4];
        #pragma unroll
        for (int mt = 0; mt < 4; mt++) {
            uint32_t addr = aBase +
                (uint32_t)(((R0 + mt * 16 + lr + khalf * 8) * PAD + k0 + kq * 8) * 2);
            ldsm4(af[mt], addr);
        }

        uint32_t bf[4][2];
        #pragma unroll
        for (int np = 0; np < 2; np++) {
            uint32_t r4[4];
            uint32_t addr = bBase +
                (uint32_t)(((C0 + np * 16 + kq * 8 + lr) * PAD + k0 + khalf * 8) * 2);
            ldsm4(r4, addr);
            bf[np * 2 + 0][0] = r4[0]; bf[np * 2 + 0][1] = r4[1];
            bf[np * 2 + 1][0] = r4[2]; bf[np * 2 + 1][1] = r4[3];
        }

        #pragma unroll
        for (int mt = 0; mt < 4; mt++)
            #pragma unroll
            for (int nt = 0; nt < 4; nt++)
                mma16816(acc[mt][nt], af[mt], bf[nt]);
    }

    // ---- ballot early-out epilogue ----
    bool diag = (ti == tj);
    int gr = l >> 2, tg = l & 3;
    #pragma unroll
    for (int mt = 0; mt < 4; mt++) {
        // branchless max over this thread's 16 values of the mt group
        float mx = acc[mt][0][0];
        #pragma unroll
        for (int nt = 0; nt < 4; nt++)
            #pragma unroll
            for (int e = 0; e < 4; e++)
                mx = fmaxf(mx, acc[mt][nt][e]);

        // warp-uniform skip: common case (no survivor in 16x32 subtile)
        if (__any_sync(0xffffffffu, mx >= SCREEN)) {
            int gi0 = ib + R0 + mt * 16 + gr;
            #pragma unroll
            for (int nt = 0; nt < 4; nt++) {
                int gj0 = jb + C0 + nt * 8 + tg * 2;
                float* c = acc[mt][nt];
                screen_push(gi0,     gj0,     c[0], diag);
                screen_push(gi0,     gj0 + 1, c[1], diag);
                screen_push(gi0 + 8, gj0,     c[2], diag);
                screen_push(gi0 + 8, gj0 + 1, c[3], diag);
            }
        }
    }
}

// ---------------------------------------------------------------------------
// Kernel 3: exact fp32 recheck (candidates from global) + per-row top-64
// with JAX stable tie-break. One warp per row.
// ---------------------------------------------------------------------------
__global__ void __launch_bounds__(256) topk_kernel(float* __restrict__ H)
{
    __shared__ float sV[8][SCAP];
    __shared__ int   sJ[8][SCAP];

    int t = threadIdx.x, w = t >> 5, l = t & 31;
    int r = blockIdx.x * 8 + w;
    const float* __restrict__ hn = g_hn;

    int m = g_ccnt[r];
    if (m > CCAP) m = CCAP;

    float a1 = hn[r * DIM + l];
    float a2 = hn[r * DIM + 32 + l];

    int cnt = 0;
    for (int p = 0; p < m; p++) {
        int j = g_candJ[r * CCAP + p];
        float s = a1 * hn[j * DIM + l] + a2 * hn[j * DIM + 32 + l];
        #pragma unroll
        for (int o = 16; o; o >>= 1)
            s += __shfl_xor_sync(0xffffffffu, s, o);
        if (s >= 0.5f && cnt < SCAP) {
            if (l == 0) { sV[w][cnt] = s; sJ[w][cnt] = j; }
            cnt++;
        }
    }
    __syncwarp();

    float* kv = sV[w];
    int*   kj = sJ[w];
    int nsel = cnt < TOPK ? cnt : TOPK;

    // selection: (value desc, index asc) — matches JAX top_k
    for (int s = 0; s < nsel; s++) {
        float bv = -1.0f; int bj = NN; int bp = -1;
        for (int p = l; p < cnt; p += 32) {
            float v = kv[p]; int j = kj[p];
            if (v > bv || (v == bv && j < bj)) { bv = v; bj = j; bp = p; }
        }
        #pragma unroll
        for (int o = 16; o; o >>= 1) {
            float ov = __shfl_xor_sync(0xffffffffu, bv, o);
            int   oj = __shfl_xor_sync(0xffffffffu, bj, o);
            int   op = __shfl_xor_sync(0xffffffffu, bp, o);
            if (ov > bv || (ov == bv && oj < bj)) { bv = ov; bj = oj; bp = op; }
        }
        if (l == 0) {
            H[s * NN + bj] = 1.0f;
            kv[bp] = -1.0f;
        }
        __syncwarp();
    }

    // fill remaining slots with zeros: ascending index, skipping survivors
    if (l == 0) {
        int s = nsel;
        int j = 0;
        while (s < TOPK) {
            bool kept = false;
            for (int p = 0; p < cnt; p++)
                if (kj[p] == j) { kept = true; break; }
            if (!kept) { H[s * NN + j] = 1.0f; s++; }
            j++;
        }
    }
}

// ---------------------------------------------------------------------------
// launch
// ---------------------------------------------------------------------------
extern "C" void kernel_launch(void* const* d_in, const int* in_sizes, int n_in,
                              void* d_out, int out_size)
{
    const int* idx    = (const int*)d_in[0];
    const float* emb  = (const float*)d_in[1];
    const float* W    = (const float*)d_in[2];
    const float* bias = (const float*)d_in[3];
    float* H          = (float*)d_out;

    hn_kernel<<<NN / 16, 256>>>(idx, emb, W, bias, H);
    sim_mma_kernel<<<NJOBS, 256>>>();
    topk_kernel<<<NN / 8, 256>>>(H);
}